// round 15
// baseline (speedup 1.0000x reference)
#include <cuda_runtime.h>
#include <cuda_fp16.h>
#include <cstdint>
#include <cstring>

#define N_ROWS 4096
#define DIM    1024
#define VOCAB  32000

#define BM 128
#define BN 256
#define BK 64
#define NKSTEP (DIM / BK)        // 16
#define STAGES 2
#define NTILE_V (VOCAB / BN)     // 125
#define NTILE_M (N_ROWS / BM)    // 32
#define NTILES (NTILE_V * NTILE_M) // 4000
#define GRID_P 296               // 2 CTAs x 148 SMs, persistent

#define LDA_B 144                // bytes per smem row (64 f16 = 128B + 16 pad)
#define A_STG_BYTES (BM * LDA_B) // 18432
#define B_STG_BYTES (BN * LDA_B) // 36864
#define STG_BYTES (A_STG_BYTES + B_STG_BYTES)  // 55296
#define SMEM_RED  (STAGES * STG_BYTES)         // 110592
#define SMEM_BYTES (SMEM_RED + 128)            // 110720 (x2 CTA = 221440 <= 227KB)

// ---- scratch ----
__device__ __align__(16) __half g_xh[N_ROWS * DIM];
__device__ __align__(16) __half g_wh[VOCAB * DIM];
__device__ float g_sumexp[N_ROWS];
__device__ float g_tgt[N_ROWS];
__device__ float g_sumlogit;
__device__ int   g_y[N_ROWS];

// ================= helpers =================
__device__ __forceinline__ uint32_t smem_u32(const void* p) {
    uint32_t a;
    asm("{ .reg .u64 t; cvta.to.shared.u64 t, %1; cvt.u32.u64 %0, t; }" : "=r"(a) : "l"(p));
    return a;
}
__device__ __forceinline__ uint32_t pack_h2(float lo, float hi) {
    __half2 t = __floats2half2_rn(lo, hi);
    uint32_t u;
    memcpy(&u, &t, 4);
    return u;
}
// cp.async with compile-time dst/src immediates: 1 base reg each, no IMAD chains
template<int DOFF, int SOFF>
__device__ __forceinline__ void cp16o(uint32_t dst, const void* src) {
    asm volatile("cp.async.cg.shared.global [%0+%2], [%1+%3], 16;"
                 :: "r"(dst), "l"(src), "n"(DOFF), "n"(SOFF) : "memory");
}
__device__ __forceinline__ void cp_commit() {
    asm volatile("cp.async.commit_group;" ::: "memory");
}
template<int N>
__device__ __forceinline__ void cp_wait() {
    asm volatile("cp.async.wait_group %0;" :: "n"(N) : "memory");
}
// ldmatrix x4 with compile-time immediate offset
template<int OFF>
__device__ __forceinline__ void ldm4o(uint32_t* r, uint32_t base) {
    asm volatile("ldmatrix.sync.aligned.m8n8.x4.shared.b16 {%0,%1,%2,%3}, [%4+%5];"
                 : "=r"(r[0]), "=r"(r[1]), "=r"(r[2]), "=r"(r[3])
                 : "r"(base), "n"(OFF));
}
// f16 accumulate; NON-volatile so ptxas can interleave with ldmatrix
__device__ __forceinline__ void mma16816h(uint32_t* c, const uint32_t* a, uint32_t b0, uint32_t b1) {
    asm("mma.sync.aligned.m16n8k16.row.col.f16.f16.f16.f16 "
        "{%0,%1}, {%2,%3,%4,%5}, {%6,%7}, {%0,%1};"
        : "+r"(c[0]), "+r"(c[1])
        : "r"(a[0]), "r"(a[1]), "r"(a[2]), "r"(a[3]), "r"(b0), "r"(b1));
}

// one stage load: A 128 rows (4 chunks), B 256 rows (8 chunks), base+imm form
__device__ __forceinline__ void load_stage(uint32_t dA, uint32_t dB,
                                           const __half* gA, const __half* gB) {
    cp16o<0 * 4608, 0 * 65536>(dA, gA);
    cp16o<1 * 4608, 1 * 65536>(dA, gA);
    cp16o<2 * 4608, 2 * 65536>(dA, gA);
    cp16o<3 * 4608, 3 * 65536>(dA, gA);
    cp16o<0 * 4608, 0 * 65536>(dB, gB);
    cp16o<1 * 4608, 1 * 65536>(dB, gB);
    cp16o<2 * 4608, 2 * 65536>(dB, gB);
    cp16o<3 * 4608, 3 * 65536>(dB, gB);
    cp16o<4 * 4608, 4 * 65536>(dB, gB);
    cp16o<5 * 4608, 5 * 65536>(dB, gB);
    cp16o<6 * 4608, 6 * 65536>(dB, gB);
    cp16o<7 * 4608, 7 * 65536>(dB, gB);
    cp_commit();
}

// ================= setup (zero + y-detect + y-gather) =================
__global__ void setup_kernel(const void* __restrict__ y) {
    __shared__ int s_flag;
    const int tid = threadIdx.x;
    int found = 0;
    const unsigned int* yw = (const unsigned int*)y;
    for (int j = tid; j < 2048; j += blockDim.x)
        if (yw[2 * j + 1] != 0u) found = 1;
    int any = __syncthreads_or(found);
    if (tid == 0) { s_flag = any; g_sumlogit = 0.f; }
    __syncthreads();
    const int isI32 = s_flag;
    for (int i = tid; i < N_ROWS; i += blockDim.x) {
        g_sumexp[i] = 0.f;
        g_tgt[i] = 0.f;
        g_y[i] = isI32 ? ((const int*)y)[i] : (int)(((const long long*)y)[i]);
    }
}

// ================= converts (fp32 -> f16) =================
__global__ void convert_x_kernel(const float4* __restrict__ src) {
    uint4* dst = (uint4*)g_xh;
    const int n8 = N_ROWS * DIM / 8;
    const int stride = gridDim.x * blockDim.x;
    for (int i = blockIdx.x * blockDim.x + threadIdx.x; i < n8; i += stride) {
        float4 v0 = src[2 * i], v1 = src[2 * i + 1];
        uint4 o;
        o.x = pack_h2(v0.x, v0.y);
        o.y = pack_h2(v0.z, v0.w);
        o.z = pack_h2(v1.x, v1.y);
        o.w = pack_h2(v1.z, v1.w);
        dst[i] = o;
    }
}

__global__ void convert_w_kernel(const float4* __restrict__ src) {
    uint4* dst = (uint4*)g_wh;
    const int n8 = VOCAB * DIM / 8;
    const int stride = gridDim.x * blockDim.x;
    for (int i = blockIdx.x * blockDim.x + threadIdx.x; i < n8; i += stride) {
        float4 v0 = src[2 * i], v1 = src[2 * i + 1];
        uint4 o;
        o.x = pack_h2(v0.x, v0.y);
        o.y = pack_h2(v0.z, v0.w);
        o.z = pack_h2(v1.x, v1.y);
        o.w = pack_h2(v1.z, v1.w);
        dst[i] = o;
    }
}

// one kk sub-step: 8 LDSM.x4 + 32 HMMA, all offsets immediate
#define MAINKK(KK) do {                                                        \
    uint32_t a[4][4];                                                          \
    ldm4o<0 * 2304 + (KK) * 32>(a[0], aab);                                    \
    ldm4o<1 * 2304 + (KK) * 32>(a[1], aab);                                    \
    ldm4o<2 * 2304 + (KK) * 32>(a[2], aab);                                    \
    ldm4o<3 * 2304 + (KK) * 32>(a[3], aab);                                    \
    {                                                                          \
        uint32_t b[4];                                                         \
        ldm4o<0 * 2304 + (KK) * 32>(b, bbb);                                   \
        mma16816h(acc[0][0], a[0], b[0], b[2]); mma16816h(acc[0][1], a[0], b[1], b[3]); \
        mma16816h(acc[1][0], a[1], b[0], b[2]); mma16816h(acc[1][1], a[1], b[1], b[3]); \
        mma16816h(acc[2][0], a[2], b[0], b[2]); mma16816h(acc[2][1], a[2], b[1], b[3]); \
        mma16816h(acc[3][0], a[3], b[0], b[2]); mma16816h(acc[3][1], a[3], b[1], b[3]); \
    }                                                                          \
    {                                                                          \
        uint32_t b[4];                                                         \
        ldm4o<1 * 2304 + (KK) * 32>(b, bbb);                                   \
        mma16816h(acc[0][2], a[0], b[0], b[2]); mma16816h(acc[0][3], a[0], b[1], b[3]); \
        mma16816h(acc[1][2], a[1], b[0], b[2]); mma16816h(acc[1][3], a[1], b[1], b[3]); \
        mma16816h(acc[2][2], a[2], b[0], b[2]); mma16816h(acc[2][3], a[2], b[1], b[3]); \
        mma16816h(acc[3][2], a[3], b[0], b[2]); mma16816h(acc[3][3], a[3], b[1], b[3]); \
    }                                                                          \
    {                                                                          \
        uint32_t b[4];                                                         \
        ldm4o<2 * 2304 + (KK) * 32>(b, bbb);                                   \
        mma16816h(acc[0][4], a[0], b[0], b[2]); mma16816h(acc[0][5], a[0], b[1], b[3]); \
        mma16816h(acc[1][4], a[1], b[0], b[2]); mma16816h(acc[1][5], a[1], b[1], b[3]); \
        mma16816h(acc[2][4], a[2], b[0], b[2]); mma16816h(acc[2][5], a[2], b[1], b[3]); \
        mma16816h(acc[3][4], a[3], b[0], b[2]); mma16816h(acc[3][5], a[3], b[1], b[3]); \
    }                                                                          \
    {                                                                          \
        uint32_t b[4];                                                         \
        ldm4o<3 * 2304 + (KK) * 32>(b, bbb);                                   \
        mma16816h(acc[0][6], a[0], b[0], b[2]); mma16816h(acc[0][7], a[0], b[1], b[3]); \
        mma16816h(acc[1][6], a[1], b[0], b[2]); mma16816h(acc[1][7], a[1], b[1], b[3]); \
        mma16816h(acc[2][6], a[2], b[0], b[2]); mma16816h(acc[2][7], a[2], b[1], b[3]); \
        mma16816h(acc[3][6], a[3], b[0], b[2]); mma16816h(acc[3][7], a[3], b[1], b[3]); \
    }                                                                          \
} while (0)

// ================= fused GEMM + softmax stats (persistent) =================
// Grid 296 persistent CTAs, 256 threads = 8 warps (2 M x 4 N). Warp tile 64x64.
// Each CTA loops tiles t = bid, bid+296, ... ; next tile's stage-0 load is
// issued BEFORE the epilogue so exp/atomics hide the prologue latency.
__global__ void __launch_bounds__(256, 2) fused_kernel() {
    extern __shared__ char smem[];
    const uint32_t sb0 = smem_u32(smem);
    const int tid = threadIdx.x;
    const int wid = tid >> 5, lid = tid & 31;
    const int wm = wid & 1;       // 2 M-warps -> 64 rows each
    const int wn = wid >> 1;      // 4 N-warps -> 64 cols each

    const uint32_t dA0 = sb0 + (tid >> 3) * LDA_B + (tid & 7) * 16;
    const uint32_t dB0 = dA0 + A_STG_BYTES;
    const uint32_t a_base = sb0 + (uint32_t)(wm * 64 + (lid & 15)) * LDA_B + (uint32_t)((lid >> 4) * 16);
    const uint32_t b_base = sb0 + A_STG_BYTES + (uint32_t)(wn * 64 + (lid & 15)) * LDA_B + (uint32_t)((lid >> 4) * 16);
    const size_t thr_a_off = (size_t)(tid >> 3) * DIM + (tid & 7) * 8;

    float sl_all = 0.f;

    int t = blockIdx.x;
    // prologue: stage-0 load of first tile
    {
        const int v0 = (t % NTILE_V) * BN;
        const int m0 = (t / NTILE_V) * BM;
        load_stage(dA0, dB0,
                   g_xh + (size_t)m0 * DIM + thr_a_off,
                   g_wh + (size_t)v0 * DIM + thr_a_off);
    }

#pragma unroll 1
    for (; t < NTILES; t += GRID_P) {
        const int v0 = (t % NTILE_V) * BN;
        const int m0 = (t / NTILE_V) * BM;
        const __half* gA = g_xh + (size_t)m0 * DIM + thr_a_off + BK;
        const __half* gB = g_wh + (size_t)v0 * DIM + thr_a_off + BK;

        uint32_t acc[4][8][2];
#pragma unroll
        for (int mi = 0; mi < 4; mi++)
#pragma unroll
            for (int ni = 0; ni < 8; ni++) { acc[mi][ni][0] = 0u; acc[mi][ni][1] = 0u; }

#pragma unroll 1
        for (int k = 0; k < NKSTEP; k++) {
            cp_wait<0>();
            __syncthreads();
            if (k + 1 < NKSTEP) {
                const uint32_t ss = ((k + 1) & 1) * STG_BYTES;
                load_stage(dA0 + ss, dB0 + ss, gA, gB);
                gA += BK; gB += BK;
            }
            const uint32_t so = (k & 1) * STG_BYTES;
            const uint32_t aab = a_base + so;
            const uint32_t bbb = b_base + so;

            MAINKK(0);
            MAINKK(1);
            MAINKK(2);
            MAINKK(3);
        }

        // issue next tile's stage-0 load NOW; the epilogue below hides it.
        // (stage 0 was last read at k=14, fenced by k=15's __syncthreads;
        //  in-flight warps in k=15 read stage 1 only.)
        const int tn = t + GRID_P;
        if (tn < NTILES) {
            const int v0n = (tn % NTILE_V) * BN;
            const int m0n = (tn / NTILE_V) * BM;
            load_stage(dA0, dB0,
                       g_xh + (size_t)m0n * DIM + thr_a_off,
                       g_wh + (size_t)v0n * DIM + thr_a_off);
        }

        // ---- epilogue for tile t: reduce directly from f16 accumulators ----
        const int q = lid >> 2;
        const int qpos = lid & 3;
#pragma unroll
        for (int mi = 0; mi < 4; mi++) {
#pragma unroll
            for (int pair = 0; pair < 2; pair++) {
                const int mrow = m0 + wm * 64 + mi * 16 + q + pair * 8;
                float se = 0.f, sl = 0.f;
#pragma unroll
                for (int ni = 0; ni < 8; ni++) {
                    __half2 h;
                    memcpy(&h, &acc[mi][ni][pair], 4);
                    float2 v = __half22float2(h);
                    se += __expf(v.x) + __expf(v.y);
                    sl += v.x + v.y;
                }
                sl_all += sl;
                se += __shfl_xor_sync(0xffffffffu, se, 1);
                se += __shfl_xor_sync(0xffffffffu, se, 2);
                if (qpos == 0) atomicAdd(&g_sumexp[mrow], se);

                const int c = g_y[mrow] - v0 - wn * 64;   // 0..63 if in this warp's cols
                if (c >= 0 && c < 64) {
                    const int ni = c >> 3, w = c & 7;
                    if (qpos == (w >> 1)) {
                        __half2 h;
                        memcpy(&h, &acc[mi][ni][pair], 4);
                        float2 v = __half22float2(h);
                        g_tgt[mrow] = (w & 1) ? v.y : v.x;
                    }
                }
            }
        }
    }

    // ---- one-shot sumlogit reduction for the whole CTA ----
#pragma unroll
    for (int o = 16; o; o >>= 1) sl_all += __shfl_xor_sync(0xffffffffu, sl_all, o);
    float* red = (float*)(smem + SMEM_RED);
    if (lid == 0) red[wid] = sl_all;
    __syncthreads();
    if (tid == 0) {
        float s = red[0] + red[1] + red[2] + red[3] + red[4] + red[5] + red[6] + red[7];
        atomicAdd(&g_sumlogit, s);
    }
}

// ================= finalize =================
__global__ void finalize_kernel(float* __restrict__ out) {
    __shared__ float sa[32], sb[32];
    int tid = threadIdx.x;
    float a = 0.f, b = 0.f;
    for (int i = tid; i < N_ROWS; i += blockDim.x) {
        a += logf(g_sumexp[i]);
        b += g_tgt[i];
    }
#pragma unroll
    for (int o = 16; o; o >>= 1) {
        a += __shfl_xor_sync(0xffffffffu, a, o);
        b += __shfl_xor_sync(0xffffffffu, b, o);
    }
    if ((tid & 31) == 0) { sa[tid >> 5] = a; sb[tid >> 5] = b; }
    __syncthreads();
    if (tid < 32) {
        a = sa[tid]; b = sb[tid];
#pragma unroll
        for (int o = 16; o; o >>= 1) {
            a += __shfl_xor_sync(0xffffffffu, a, o);
            b += __shfl_xor_sync(0xffffffffu, b, o);
        }
        if (tid == 0) {
            const float invN = 1.0f / (float)N_ROWS;
            float loss = a * invN - 0.9f * (b * invN)
                       - 0.1f * g_sumlogit / ((float)N_ROWS * (float)VOCAB);
            out[0] = loss;
        }
    }
}

extern "C" void kernel_launch(void* const* d_in, const int* in_sizes, int n_in,
                              void* d_out, int out_size) {
    const float* x = (const float*)d_in[0];
    const float* W = (const float*)d_in[1];
    const void*  y = d_in[2];
    float* out = (float*)d_out;

    (void)cudaFuncSetAttribute(fused_kernel, cudaFuncAttributeMaxDynamicSharedMemorySize, SMEM_BYTES);

    setup_kernel<<<1, 1024>>>(y);
    convert_x_kernel<<<148 * 8, 256>>>((const float4*)x);
    convert_w_kernel<<<148 * 16, 256>>>((const float4*)W);

    fused_kernel<<<GRID_P, 256, SMEM_BYTES>>>();

    finalize_kernel<<<1, 1024>>>(out);
}

// round 16
// speedup vs baseline: 1.4963x; 1.4963x over previous
#include <cuda_runtime.h>
#include <cuda_fp16.h>
#include <cstdint>
#include <cstring>

#define N_ROWS 4096
#define DIM    1024
#define VOCAB  32000

#define BM 128
#define BN 256
#define BK 64
#define NKSTEP (DIM / BK)        // 16
#define STAGES 2

#define LDA_B 144                // bytes per smem row (64 f16 = 128B + 16 pad)
#define A_STG_BYTES (BM * LDA_B) // 18432
#define B_STG_BYTES (BN * LDA_B) // 36864
#define STG_BYTES (A_STG_BYTES + B_STG_BYTES)  // 55296
#define SMEM_RED  (STAGES * STG_BYTES)         // 110592
#define SMEM_BYTES (SMEM_RED + 128)            // 110720 (x2 CTA = 221440 <= 227KB)

// ---- scratch ----
__device__ __align__(16) __half g_xh[N_ROWS * DIM];
__device__ __align__(16) __half g_wh[VOCAB * DIM];
__device__ float g_sumexp[N_ROWS];
__device__ float g_tgt[N_ROWS];
__device__ float g_sumlogit;
__device__ int   g_y[N_ROWS];

// ================= helpers =================
__device__ __forceinline__ uint32_t smem_u32(const void* p) {
    uint32_t a;
    asm("{ .reg .u64 t; cvta.to.shared.u64 t, %1; cvt.u32.u64 %0, t; }" : "=r"(a) : "l"(p));
    return a;
}
__device__ __forceinline__ uint32_t pack_h2(float lo, float hi) {
    __half2 t = __floats2half2_rn(lo, hi);
    uint32_t u;
    memcpy(&u, &t, 4);
    return u;
}
// cp.async with compile-time dst/src immediates: 1 base reg each, no IMAD chains
template<int DOFF, int SOFF>
__device__ __forceinline__ void cp16o(uint32_t dst, const void* src) {
    asm volatile("cp.async.cg.shared.global [%0+%2], [%1+%3], 16;"
                 :: "r"(dst), "l"(src), "n"(DOFF), "n"(SOFF) : "memory");
}
__device__ __forceinline__ void cp_commit() {
    asm volatile("cp.async.commit_group;" ::: "memory");
}
template<int N>
__device__ __forceinline__ void cp_wait() {
    asm volatile("cp.async.wait_group %0;" :: "n"(N) : "memory");
}
// ldmatrix x4 with compile-time immediate offset
template<int OFF>
__device__ __forceinline__ void ldm4o(uint32_t* r, uint32_t base) {
    asm volatile("ldmatrix.sync.aligned.m8n8.x4.shared.b16 {%0,%1,%2,%3}, [%4+%5];"
                 : "=r"(r[0]), "=r"(r[1]), "=r"(r[2]), "=r"(r[3])
                 : "r"(base), "n"(OFF));
}
// f16 accumulate; NON-volatile so ptxas can interleave with ldmatrix
__device__ __forceinline__ void mma16816h(uint32_t* c, const uint32_t* a, uint32_t b0, uint32_t b1) {
    asm("mma.sync.aligned.m16n8k16.row.col.f16.f16.f16.f16 "
        "{%0,%1}, {%2,%3,%4,%5}, {%6,%7}, {%0,%1};"
        : "+r"(c[0]), "+r"(c[1])
        : "r"(a[0]), "r"(a[1]), "r"(a[2]), "r"(a[3]), "r"(b0), "r"(b1));
}

// one stage load: A 128 rows (4 chunks), B 256 rows (8 chunks), base+imm form
__device__ __forceinline__ void load_stage(uint32_t dA, uint32_t dB,
                                           const __half* gA, const __half* gB) {
    cp16o<0 * 4608, 0 * 65536>(dA, gA);
    cp16o<1 * 4608, 1 * 65536>(dA, gA);
    cp16o<2 * 4608, 2 * 65536>(dA, gA);
    cp16o<3 * 4608, 3 * 65536>(dA, gA);
    cp16o<0 * 4608, 0 * 65536>(dB, gB);
    cp16o<1 * 4608, 1 * 65536>(dB, gB);
    cp16o<2 * 4608, 2 * 65536>(dB, gB);
    cp16o<3 * 4608, 3 * 65536>(dB, gB);
    cp16o<4 * 4608, 4 * 65536>(dB, gB);
    cp16o<5 * 4608, 5 * 65536>(dB, gB);
    cp16o<6 * 4608, 6 * 65536>(dB, gB);
    cp16o<7 * 4608, 7 * 65536>(dB, gB);
    cp_commit();
}

// ================= setup (zero + y-detect + y-gather) =================
__global__ void setup_kernel(const void* __restrict__ y) {
    __shared__ int s_flag;
    const int tid = threadIdx.x;
    int found = 0;
    const unsigned int* yw = (const unsigned int*)y;
    for (int j = tid; j < 2048; j += blockDim.x)
        if (yw[2 * j + 1] != 0u) found = 1;
    int any = __syncthreads_or(found);
    if (tid == 0) { s_flag = any; g_sumlogit = 0.f; }
    __syncthreads();
    const int isI32 = s_flag;
    for (int i = tid; i < N_ROWS; i += blockDim.x) {
        g_sumexp[i] = 0.f;
        g_tgt[i] = 0.f;
        g_y[i] = isI32 ? ((const int*)y)[i] : (int)(((const long long*)y)[i]);
    }
}

// ================= converts (fp32 -> f16) =================
__global__ void convert_x_kernel(const float4* __restrict__ src) {
    uint4* dst = (uint4*)g_xh;
    const int n8 = N_ROWS * DIM / 8;
    const int stride = gridDim.x * blockDim.x;
    for (int i = blockIdx.x * blockDim.x + threadIdx.x; i < n8; i += stride) {
        float4 v0 = src[2 * i], v1 = src[2 * i + 1];
        uint4 o;
        o.x = pack_h2(v0.x, v0.y);
        o.y = pack_h2(v0.z, v0.w);
        o.z = pack_h2(v1.x, v1.y);
        o.w = pack_h2(v1.z, v1.w);
        dst[i] = o;
    }
}

__global__ void convert_w_kernel(const float4* __restrict__ src) {
    uint4* dst = (uint4*)g_wh;
    const int n8 = VOCAB * DIM / 8;
    const int stride = gridDim.x * blockDim.x;
    for (int i = blockIdx.x * blockDim.x + threadIdx.x; i < n8; i += stride) {
        float4 v0 = src[2 * i], v1 = src[2 * i + 1];
        uint4 o;
        o.x = pack_h2(v0.x, v0.y);
        o.y = pack_h2(v0.z, v0.w);
        o.z = pack_h2(v1.x, v1.y);
        o.w = pack_h2(v1.z, v1.w);
        dst[i] = o;
    }
}

// one kk sub-step: 8 LDSM.x4 + 32 HMMA, all offsets immediate
#define MAINKK(KK) do {                                                        \
    uint32_t a[4][4];                                                          \
    ldm4o<0 * 2304 + (KK) * 32>(a[0], aab);                                    \
    ldm4o<1 * 2304 + (KK) * 32>(a[1], aab);                                    \
    ldm4o<2 * 2304 + (KK) * 32>(a[2], aab);                                    \
    ldm4o<3 * 2304 + (KK) * 32>(a[3], aab);                                    \
    {                                                                          \
        uint32_t b[4];                                                         \
        ldm4o<0 * 2304 + (KK) * 32>(b, bbb);                                   \
        mma16816h(acc[0][0], a[0], b[0], b[2]); mma16816h(acc[0][1], a[0], b[1], b[3]); \
        mma16816h(acc[1][0], a[1], b[0], b[2]); mma16816h(acc[1][1], a[1], b[1], b[3]); \
        mma16816h(acc[2][0], a[2], b[0], b[2]); mma16816h(acc[2][1], a[2], b[1], b[3]); \
        mma16816h(acc[3][0], a[3], b[0], b[2]); mma16816h(acc[3][1], a[3], b[1], b[3]); \
    }                                                                          \
    {                                                                          \
        uint32_t b[4];                                                         \
        ldm4o<1 * 2304 + (KK) * 32>(b, bbb);                                   \
        mma16816h(acc[0][2], a[0], b[0], b[2]); mma16816h(acc[0][3], a[0], b[1], b[3]); \
        mma16816h(acc[1][2], a[1], b[0], b[2]); mma16816h(acc[1][3], a[1], b[1], b[3]); \
        mma16816h(acc[2][2], a[2], b[0], b[2]); mma16816h(acc[2][3], a[2], b[1], b[3]); \
        mma16816h(acc[3][2], a[3], b[0], b[2]); mma16816h(acc[3][3], a[3], b[1], b[3]); \
    }                                                                          \
    {                                                                          \
        uint32_t b[4];                                                         \
        ldm4o<2 * 2304 + (KK) * 32>(b, bbb);                                   \
        mma16816h(acc[0][4], a[0], b[0], b[2]); mma16816h(acc[0][5], a[0], b[1], b[3]); \
        mma16816h(acc[1][4], a[1], b[0], b[2]); mma16816h(acc[1][5], a[1], b[1], b[3]); \
        mma16816h(acc[2][4], a[2], b[0], b[2]); mma16816h(acc[2][5], a[2], b[1], b[3]); \
        mma16816h(acc[3][4], a[3], b[0], b[2]); mma16816h(acc[3][5], a[3], b[1], b[3]); \
    }                                                                          \
    {                                                                          \
        uint32_t b[4];                                                         \
        ldm4o<3 * 2304 + (KK) * 32>(b, bbb);                                   \
        mma16816h(acc[0][6], a[0], b[0], b[2]); mma16816h(acc[0][7], a[0], b[1], b[3]); \
        mma16816h(acc[1][6], a[1], b[0], b[2]); mma16816h(acc[1][7], a[1], b[1], b[3]); \
        mma16816h(acc[2][6], a[2], b[0], b[2]); mma16816h(acc[2][7], a[2], b[1], b[3]); \
        mma16816h(acc[3][6], a[3], b[0], b[2]); mma16816h(acc[3][7], a[3], b[1], b[3]); \
    }                                                                          \
} while (0)

// ================= fused GEMM + softmax stats =================
// Grid (125, 32), 256 threads = 8 warps (2 M x 4 N). Warp tile 64x64.
// f16 accumulators; 2 CTAs/SM; 2-stage double buffer; base+imm addressing.
// Epilogue uses ex2.approx.f16x2 (h2exp2) — 2 exps per MUFU instruction.
__global__ void __launch_bounds__(256, 2) fused_kernel() {
    extern __shared__ char smem[];
    const uint32_t sb0 = smem_u32(smem);
    const int tid = threadIdx.x;
    const int wid = tid >> 5, lid = tid & 31;
    const int wm = wid & 1;       // 2 M-warps -> 64 rows each
    const int wn = wid >> 1;      // 4 N-warps -> 64 cols each
    const int v0 = blockIdx.x * BN;
    const int m0 = blockIdx.y * BM;

    if (tid == 0) *(float*)(smem + SMEM_RED) = 0.f;

    uint32_t acc[4][8][2];          // 4 Mi x 8 n8 x 2 = 64 regs
#pragma unroll
    for (int mi = 0; mi < 4; mi++)
#pragma unroll
        for (int ni = 0; ni < 8; ni++) { acc[mi][ni][0] = 0u; acc[mi][ni][1] = 0u; }

    // per-thread base pointers (advance by 64 halves = 128 B per k-step)
    const __half* gA = g_xh + (size_t)(m0 + (tid >> 3)) * DIM + (tid & 7) * 8;
    const __half* gB = g_wh + (size_t)(v0 + (tid >> 3)) * DIM + (tid & 7) * 8;
    const uint32_t dA0 = sb0 + (tid >> 3) * LDA_B + (tid & 7) * 16;
    const uint32_t dB0 = dA0 + A_STG_BYTES;

    load_stage(dA0, dB0, gA, gB);
    gA += BK; gB += BK;

    const uint32_t a_base = sb0 + (uint32_t)(wm * 64 + (lid & 15)) * LDA_B + (uint32_t)((lid >> 4) * 16);
    const uint32_t b_base = sb0 + A_STG_BYTES + (uint32_t)(wn * 64 + (lid & 15)) * LDA_B + (uint32_t)((lid >> 4) * 16);

    for (int k = 0; k < NKSTEP; k++) {
        cp_wait<0>();
        __syncthreads();
        if (k + 1 < NKSTEP) {
            const uint32_t ss = ((k + 1) & 1) * STG_BYTES;
            load_stage(dA0 + ss, dB0 + ss, gA, gB);
            gA += BK; gB += BK;
        }
        const uint32_t so = (k & 1) * STG_BYTES;
        const uint32_t aab = a_base + so;
        const uint32_t bbb = b_base + so;

        MAINKK(0);
        MAINKK(1);
        MAINKK(2);
        MAINKK(3);
    }

    // ---- epilogue: reduce from f16 accumulators via ex2.approx.f16x2 ----
    const int q = lid >> 2;
    const int qpos = lid & 3;
    const __half2 l2e = __float2half2_rn(1.44269504f);   // log2(e)
    float sl_tot = 0.f;

#pragma unroll
    for (int mi = 0; mi < 4; mi++) {
#pragma unroll
        for (int pair = 0; pair < 2; pair++) {
            const int mrow = m0 + wm * 64 + mi * 16 + q + pair * 8;
            __half2 se2 = __float2half2_rn(0.f);
            __half2 sl2 = __float2half2_rn(0.f);
#pragma unroll
            for (int ni = 0; ni < 8; ni++) {
                __half2 h;
                memcpy(&h, &acc[mi][ni][pair], 4);
                sl2 = __hadd2(sl2, h);
                se2 = __hadd2(se2, h2exp2(__hmul2(h, l2e)));
            }
            float2 sev = __half22float2(se2);
            float se = sev.x + sev.y;
            float2 slv = __half22float2(sl2);
            sl_tot += slv.x + slv.y;

            se += __shfl_xor_sync(0xffffffffu, se, 1);
            se += __shfl_xor_sync(0xffffffffu, se, 2);
            if (qpos == 0) atomicAdd(&g_sumexp[mrow], se);

            const int c = g_y[mrow] - v0 - wn * 64;   // 0..63 if in this warp's cols
            if (c >= 0 && c < 64) {
                const int ni = c >> 3, w = c & 7;
                if (qpos == (w >> 1)) {
                    __half2 h;
                    memcpy(&h, &acc[mi][ni][pair], 4);
                    float2 v = __half22float2(h);
                    g_tgt[mrow] = (w & 1) ? v.y : v.x;
                }
            }
        }
    }

#pragma unroll
    for (int o = 16; o; o >>= 1) sl_tot += __shfl_xor_sync(0xffffffffu, sl_tot, o);
    if (lid == 0) atomicAdd((float*)(smem + SMEM_RED), sl_tot);
    __syncthreads();
    if (tid == 0) atomicAdd(&g_sumlogit, *(float*)(smem + SMEM_RED));
}

// ================= finalize =================
__global__ void finalize_kernel(float* __restrict__ out) {
    __shared__ float sa[32], sb[32];
    int tid = threadIdx.x;
    float a = 0.f, b = 0.f;
    for (int i = tid; i < N_ROWS; i += blockDim.x) {
        a += logf(g_sumexp[i]);
        b += g_tgt[i];
    }
#pragma unroll
    for (int o = 16; o; o >>= 1) {
        a += __shfl_xor_sync(0xffffffffu, a, o);
        b += __shfl_xor_sync(0xffffffffu, b, o);
    }
    if ((tid & 31) == 0) { sa[tid >> 5] = a; sb[tid >> 5] = b; }
    __syncthreads();
    if (tid < 32) {
        a = sa[tid]; b = sb[tid];
#pragma unroll
        for (int o = 16; o; o >>= 1) {
            a += __shfl_xor_sync(0xffffffffu, a, o);
            b += __shfl_xor_sync(0xffffffffu, b, o);
        }
        if (tid == 0) {
            const float invN = 1.0f / (float)N_ROWS;
            float loss = a * invN - 0.9f * (b * invN)
                       - 0.1f * g_sumlogit / ((float)N_ROWS * (float)VOCAB);
            out[0] = loss;
        }
    }
}

extern "C" void kernel_launch(void* const* d_in, const int* in_sizes, int n_in,
                              void* d_out, int out_size) {
    const float* x = (const float*)d_in[0];
    const float* W = (const float*)d_in[1];
    const void*  y = d_in[2];
    float* out = (float*)d_out;

    (void)cudaFuncSetAttribute(fused_kernel, cudaFuncAttributeMaxDynamicSharedMemorySize, SMEM_BYTES);

    setup_kernel<<<1, 1024>>>(y);
    convert_x_kernel<<<148 * 8, 256>>>((const float4*)x);
    convert_w_kernel<<<148 * 16, 256>>>((const float4*)W);

    dim3 grid(VOCAB / BN, N_ROWS / BM);   // 125 x 32 = 4000 CTAs
    fused_kernel<<<grid, 256, SMEM_BYTES>>>();

    finalize_kernel<<<1, 1024>>>(out);
}